// round 4
// baseline (speedup 1.0000x reference)
#include <cuda_runtime.h>

#define BB 2
#define NCH 7
#define VV 2097152          // 32*256*256
#define NI 16
#define NSG 17
#define NBINS 4096
#define SLOTS 4

// accumulator layout (floats)
#define OFF_CNT   0          // BB*NSG
#define OFF_SSUM  34         // BB*NSG*3
#define OFF_SSQ   136
#define OFF_XYZ   238
#define OFF_CCNT  340
#define OFF_CXYZ  374
#define OFF_VAR   476        // BB
#define OFF_SBG   478
#define OFF_SFG   480
#define OFF_ILOSS 482
#define OFF_S     484        // BB*NI*3
#define OFF_CEN   580        // BB*NI*3
#define ACC_N     676

__device__ float g_acc[ACC_N];                              // zero-init; self-cleaning
__device__ unsigned g_hist[BB * NI * 2 * NBINS * SLOTS];    // [b][n][fg][bin][slot] 4MB

__device__ __forceinline__ float fast_tanh(float x) {
    float r;
    asm("tanh.approx.f32 %0, %1;" : "=f"(r) : "f"(x));
    return r;
}

// ---------------------------------------------------------------- stats
// Per-warp fixed-point packed accumulators (5 u64 per id), exact bounds for
// <=256 voxels per warp. Decoded and merged at block end.
// grid (1024, BB), 256 threads, each thread exactly 8 consecutive voxels.
__global__ void __launch_bounds__(256) k_stats(const float* __restrict__ pred,
                                               const int* __restrict__ inst,
                                               const int* __restrict__ cent) {
    int b = blockIdx.y;
    __shared__ unsigned long long wacc[8][NSG][5];
    __shared__ float sm[NSG * 10];
    int tid = threadIdx.x;
    int warp = tid >> 5, lane = tid & 31;

    for (int j = tid; j < 8 * NSG * 5; j += 256)
        ((unsigned long long*)wacc)[j] = 0ull;
    for (int j = tid; j < NSG * 10; j += 256) sm[j] = 0.0f;
    __syncthreads();

    const float* sig = pred + ((size_t)b * NCH + 3) * VV;
    const int* ib = inst + (size_t)b * VV;
    const int* cb = cent + (size_t)b * VV;

    int v0 = (blockIdx.x * 256 + tid) * 8;
#pragma unroll
    for (int g = 0; g < 2; g++) {
        int vb = v0 + g * 4;
        float4 f0 = *(const float4*)(sig + vb);
        float4 f1 = *(const float4*)(sig + VV + vb);
        float4 f2 = *(const float4*)(sig + 2 * VV + vb);
        int4 iv = *(const int4*)(ib + vb);
        int4 cv = *(const int4*)(cb + vb);
        float a0[4] = {f0.x, f0.y, f0.z, f0.w};
        float a1[4] = {f1.x, f1.y, f1.z, f1.w};
        float a2[4] = {f2.x, f2.y, f2.z, f2.w};
        int ia[4] = {iv.x, iv.y, iv.z, iv.w};
        int ca[4] = {cv.x, cv.y, cv.z, cv.w};
#pragma unroll
        for (int k = 0; k < 4; k++) {
            int v = vb + k;
            int id = ia[k];
            float s0 = fminf(fmaxf(a0[k], -15.9f), 15.9f);
            float s1 = fminf(fmaxf(a1[k], -15.9f), 15.9f);
            float s2 = fminf(fmaxf(a2[k], -15.9f), 15.9f);
            float x = (float)(v & 255) * (1.0f / 1023.0f);
            float y = (float)((v >> 8) & 255) * (1.0f / 1023.0f);
            float z = (float)(v >> 16) * (1.0f / 31.0f);
            unsigned long long* base = wacc[warp][id];
            unsigned xq = __float2uint_rn(x * 4194304.0f);       // 2^22
            unsigned yq = __float2uint_rn(y * 4194304.0f);
            unsigned zq = __float2uint_rn(z * 2097152.0f);       // 2^21
            unsigned q0 = __float2uint_rn((s0 + 16.0f) * 65536.0f);
            unsigned q1 = __float2uint_rn((s1 + 16.0f) * 65536.0f);
            unsigned q2 = __float2uint_rn((s2 + 16.0f) * 65536.0f);
            unsigned r0 = __float2uint_rn(s0 * s0 * 8192.0f);
            unsigned r1 = __float2uint_rn(s1 * s1 * 8192.0f);
            unsigned r2 = __float2uint_rn(s2 * s2 * 8192.0f);
            atomicAdd(&base[0], (1ull << 40) | (unsigned long long)xq);
            atomicAdd(&base[1], ((unsigned long long)yq << 32) | zq);
            atomicAdd(&base[2], ((unsigned long long)q0 << 32) | q1);
            atomicAdd(&base[3], ((unsigned long long)q2 << 32) | r0);
            atomicAdd(&base[4], ((unsigned long long)r1 << 32) | r2);
            if (ca[k] != 0) {   // centers are ~1-per-volume rare: direct global
                int bi = b * NSG + id;
                atomicAdd(&g_acc[OFF_CCNT + bi], 1.0f);
                atomicAdd(&g_acc[OFF_CXYZ + bi * 3 + 0], x);
                atomicAdd(&g_acc[OFF_CXYZ + bi * 3 + 1], y);
                atomicAdd(&g_acc[OFF_CXYZ + bi * 3 + 2], z);
            }
        }
    }
    __syncthreads();

    // decode per-warp packs -> block-level float accumulation
    if (lane < NSG) {
        unsigned long long p0 = wacc[warp][lane][0];
        unsigned long long p1 = wacc[warp][lane][1];
        unsigned long long p2 = wacc[warp][lane][2];
        unsigned long long p3 = wacc[warp][lane][3];
        unsigned long long p4 = wacc[warp][lane][4];
        float cnt = (float)(unsigned)(p0 >> 40);
        float xs = (float)(p0 & 0xFFFFFFFFFFull) * (1.0f / 4194304.0f);
        float ys = (float)(unsigned)(p1 >> 32) * (1.0f / 4194304.0f);
        float zs = (float)(unsigned)(p1) * (1.0f / 2097152.0f);
        float s0s = (float)(unsigned)(p2 >> 32) * (1.0f / 65536.0f) - 16.0f * cnt;
        float s1s = (float)(unsigned)(p2) * (1.0f / 65536.0f) - 16.0f * cnt;
        float s2s = (float)(unsigned)(p3 >> 32) * (1.0f / 65536.0f) - 16.0f * cnt;
        float r0s = (float)(unsigned)(p3) * (1.0f / 8192.0f);
        float r1s = (float)(unsigned)(p4 >> 32) * (1.0f / 8192.0f);
        float r2s = (float)(unsigned)(p4) * (1.0f / 8192.0f);
        float* d = sm + lane * 10;
        atomicAdd(d + 0, cnt);
        atomicAdd(d + 1, s0s);
        atomicAdd(d + 2, s1s);
        atomicAdd(d + 3, s2s);
        atomicAdd(d + 4, r0s);
        atomicAdd(d + 5, r1s);
        atomicAdd(d + 6, r2s);
        atomicAdd(d + 7, xs);
        atomicAdd(d + 8, ys);
        atomicAdd(d + 9, zs);
    }
    __syncthreads();
    if (tid < NSG * 10) {
        int id = tid / 10, f = tid % 10;
        float vsm = sm[tid];
        if (vsm != 0.0f) {
            int bi = b * NSG + id;
            float* dst;
            if (f == 0)      dst = &g_acc[OFF_CNT  + bi];
            else if (f < 4)  dst = &g_acc[OFF_SSUM + bi * 3 + (f - 1)];
            else if (f < 7)  dst = &g_acc[OFF_SSQ  + bi * 3 + (f - 4)];
            else             dst = &g_acc[OFF_XYZ  + bi * 3 + (f - 7)];
            atomicAdd(dst, vsm);
        }
    }
}

// ---------------------------------------------------------------- params (+ zero stats accumulators)
__global__ void k_params() {
    int t = threadIdx.x;
    if (t >= BB * NSG) return;
    int b = t / NSG, id = t % NSG;
    float cnt = g_acc[OFF_CNT + t];
    float safe = fmaxf(cnt, 1.0f);
    float varsum = 0.0f;
    float m[3];
    float xyz[3], cxyz[3];
#pragma unroll
    for (int c = 0; c < 3; c++) {
        float ss = g_acc[OFF_SSUM + t * 3 + c];
        float sq = g_acc[OFF_SSQ + t * 3 + c];
        float mm = ss / safe;
        m[c] = mm;
        varsum += (sq - 2.0f * mm * ss + cnt * mm * mm) / safe;
        xyz[c] = g_acc[OFF_XYZ + t * 3 + c];
        cxyz[c] = g_acc[OFF_CXYZ + t * 3 + c];
    }
    float ccnt = g_acc[OFF_CCNT + t];
    // zero for next graph replay
    g_acc[OFF_CNT + t] = 0.0f;
    g_acc[OFF_CCNT + t] = 0.0f;
#pragma unroll
    for (int c = 0; c < 3; c++) {
        g_acc[OFF_SSUM + t * 3 + c] = 0.0f;
        g_acc[OFF_SSQ + t * 3 + c] = 0.0f;
        g_acc[OFF_XYZ + t * 3 + c] = 0.0f;
        g_acc[OFF_CXYZ + t * 3 + c] = 0.0f;
    }
    if (id >= 1) {
        atomicAdd(&g_acc[OFF_VAR + b], varsum * (1.0f / (3.0f * NI)));
        bool one = (ccnt == 1.0f);
        int p = (b * NI + (id - 1)) * 3;
#pragma unroll
        for (int c = 0; c < 3; c++) {
            float cen = one ? cxyz[c] : xyz[c] / safe;
            g_acc[OFF_CEN + p + c] = cen;
            g_acc[OFF_S + p + c] = expf(10.0f * m[c]);
        }
    }
}

// ---------------------------------------------------------------- dist + histogram + seed loss
// grid (1024, BB, 2), 256 thr, grid-stride (2 float4 iters/thread).
// blockIdx.z selects 8 of 16 instances. Warp-aggregated histogram atomics.
__global__ void __launch_bounds__(256) k_dist(const float* __restrict__ pred,
                                              const int* __restrict__ inst,
                                              const int* __restrict__ lab) {
    int b = blockIdx.y;
    int half = blockIdx.z;

    float c0[8], c1[8], c2[8], s0[8], s1[8], s2[8];
#pragma unroll
    for (int j = 0; j < 8; j++) {
        int p = (b * NI + half * 8 + j) * 3;
        s0[j] = g_acc[OFF_S + p];
        s1[j] = g_acc[OFF_S + p + 1];
        s2[j] = g_acc[OFF_S + p + 2];
        c0[j] = g_acc[OFF_CEN + p];
        c1[j] = g_acc[OFF_CEN + p + 1];
        c2[j] = g_acc[OFF_CEN + p + 2];
    }

    const float* pb = pred + (size_t)b * NCH * VV;
    const int* ib = inst + (size_t)b * VV;
    const int* lb = lab + (size_t)b * VV;
    unsigned* hb = g_hist + (size_t)b * NI * 2 * NBINS * SLOTS;
    int lane = threadIdx.x & 31;
    int slot = (threadIdx.x >> 5) & (SLOTS - 1);   // uniform per warp

    float accbg = 0.0f, accfg = 0.0f;

    const int stride = gridDim.x * 256 * 4;
    for (int v0 = (blockIdx.x * 256 + threadIdx.x) * 4; v0 < VV; v0 += stride) {
        float4 f0 = *(const float4*)(pb + v0);
        float4 f1 = *(const float4*)(pb + VV + v0);
        float4 f2 = *(const float4*)(pb + 2 * VV + v0);
        float4 f6 = *(const float4*)(pb + 6 * VV + v0);
        int4 iv = *(const int4*)(ib + v0);
        int4 lv = make_int4(1, 1, 1, 1);
        if (half == 0) lv = *(const int4*)(lb + v0);

        float a0[4] = {f0.x, f0.y, f0.z, f0.w};
        float a1[4] = {f1.x, f1.y, f1.z, f1.w};
        float a2[4] = {f2.x, f2.y, f2.z, f2.w};
        float a6[4] = {f6.x, f6.y, f6.z, f6.w};
        int ia[4] = {iv.x, iv.y, iv.z, iv.w};
        int la[4] = {lv.x, lv.y, lv.z, lv.w};

#pragma unroll
        for (int k = 0; k < 4; k++) {
            int v = v0 + k;
            float x = (float)(v & 255) * (1.0f / 1023.0f);
            float y = (float)((v >> 8) & 255) * (1.0f / 1023.0f);
            float z = (float)(v >> 16) * (1.0f / 31.0f);
            float e0 = fast_tanh(a0[k]) + x;
            float e1 = fast_tanh(a1[k]) + y;
            float e2 = fast_tanh(a2[k]) + z;
            int id = ia[k];
            float down = 0.0f;
#pragma unroll
            for (int j = 0; j < 8; j++) {
                int n = half * 8 + j;
                float dx = e0 - c0[j], dy = e1 - c1[j], dz = e2 - c2[j];
                float arg = s0[j] * dx * dx + s1[j] * dy * dy + s2[j] * dz * dz;
                float d = __expf(-arg);
                int fg = (id == n + 1) ? 1 : 0;
                if (fg) down = d;
                float e = fg ? fmaf(-2.0f, d, 2.0f) : 2.0f * d;
                int bin = (int)(e * (NBINS * 0.5f));
                if (bin > NBINS - 1) bin = NBINS - 1;
                // warp-aggregate: lanes with same (fg,bin) -> one atomic
                int key = (fg << 12) | bin;
                unsigned mask = __match_any_sync(0xffffffffu, key);
                int leader = __ffs(mask) - 1;
                if (lane == leader) {
                    unsigned cnt = (unsigned)__popc(mask);
                    atomicAdd(&hb[((((n << 1) | fg) * NBINS + bin) << 2) | slot], cnt);
                }
            }
            float sd = 1.0f / (1.0f + __expf(-a6[k]));
            if (id > half * 8 && id <= half * 8 + 8) {
                float t = sd - down;
                accfg += t * t;
            }
            if (half == 0 && la[k] == 0) accbg += sd * sd;
        }
    }

    __shared__ float r1[256], r2[256];
    int t = threadIdx.x;
    r1[t] = accbg;
    r2[t] = accfg;
    __syncthreads();
    for (int s = 128; s > 0; s >>= 1) {
        if (t < s) { r1[t] += r1[t + s]; r2[t] += r2[t + s]; }
        __syncthreads();
    }
    if (t == 0) {
        if (half == 0) atomicAdd(&g_acc[OFF_SBG + b], r1[0]);
        atomicAdd(&g_acc[OFF_SFG + b], r2[0]);
    }
}

// ---------------------------------------------------------------- lovasz from histogram (+ zero hist)
// one block per (b,n); 256 threads; CH=16 bins/thread; shfl-based prefix scan
__global__ void __launch_bounds__(256) k_lovasz() {
    int bn = blockIdx.x;       // b*16 + n
    int b = bn >> 4;
    unsigned* HB = g_hist + (size_t)bn * 2 * NBINS * SLOTS;  // fg=0 slice
    unsigned* HF = HB + NBINS * SLOTS;                       // fg=1 slice
    const int CH = NBINS / 256;  // 16
    int t = threadIdx.x;
    int lane = t & 31, warp = t >> 5;

    // load my bins (descending error order: rank r = t*CH+i, bin = NBINS-1-r)
    float fA[CH], bA[CH];
    float locF = 0.0f, locB = 0.0f;
#pragma unroll
    for (int i = 0; i < CH; i++) {
        int bin = NBINS - 1 - (t * CH + i);
        unsigned sf = 0, sb = 0;
#pragma unroll
        for (int sl = 0; sl < SLOTS; sl++) {
            sf += HF[(bin << 2) | sl];
            sb += HB[(bin << 2) | sl];
        }
        fA[i] = (float)sf;
        bA[i] = (float)sb;
        locF += fA[i];
        locB += bA[i];
        // zero for next replay
#pragma unroll
        for (int sl = 0; sl < SLOTS; sl++) {
            HF[(bin << 2) | sl] = 0u;
            HB[(bin << 2) | sl] = 0u;
        }
    }

    // warp-level inclusive scan of (locF, locB) in thread order
    float incF = locF, incB = locB;
#pragma unroll
    for (int d = 1; d < 32; d <<= 1) {
        float vF = __shfl_up_sync(0xffffffffu, incF, d);
        float vB = __shfl_up_sync(0xffffffffu, incB, d);
        if (lane >= d) { incF += vF; incB += vB; }
    }
    __shared__ float wF[8], wB[8];
    __shared__ float sred[256];
    __shared__ int sMinR;
    if (t == 0) sMinR = NBINS;
    if (lane == 31) { wF[warp] = incF; wB[warp] = incB; }
    __syncthreads();
    float offF = 0.0f, offB = 0.0f, G = 0.0f, Btot = 0.0f;
#pragma unroll
    for (int w = 0; w < 8; w++) {
        float f = wF[w], bb = wB[w];
        if (w < warp) { offF += f; offB += bb; }
        G += f; Btot += bb;
    }
    float P = offF + incF - locF;   // exclusive prefix (fg)
    float Q = offB + incB - locB;   // exclusive prefix (bg)

    float contrib = 0.0f;
    if (G > 0.0f) {
#pragma unroll
        for (int i = 0; i < CH; i++) {
            float f = fA[i], bb = bA[i];
            if (f > 0.0f || bb > 0.0f) {
                int bin = NBINS - 1 - (t * CH + i);
                float e = ((float)bin + 0.5f) * (2.0f / NBINS);
                float gq = G + Q;
                float num = (G - P) * bb + f * gq;   // cancellation-free jacc delta
                float den = gq * (gq + bb);
                contrib += e * num / den;
                P += f;
                Q += bb;
            }
        }
    } else {  // degenerate: no fg voxels -> loss = max error present
#pragma unroll
        for (int i = 0; i < CH; i++) {
            if (fA[i] > 0.0f || bA[i] > 0.0f) {
                atomicMin(&sMinR, t * CH + i);
                break;
            }
        }
    }
    sred[t] = contrib;
    __syncthreads();
    for (int s2 = 128; s2 > 0; s2 >>= 1) {
        if (t < s2) sred[t] += sred[t + s2];
        __syncthreads();
    }
    if (t == 0) {
        float total = sred[0];
        if (G <= 0.0f && sMinR < NBINS)
            total = ((float)(NBINS - 1 - sMinR) + 0.5f) * (2.0f / NBINS);
        atomicAdd(&g_acc[OFF_ILOSS + b], total);
    }
}

// ---------------------------------------------------------------- final combine (+ zero loss accumulators)
__global__ void k_final(float* out) {
    if (threadIdx.x == 0 && blockIdx.x == 0) {
        float r = 0.0f;
        for (int b = 0; b < BB; b++) {
            float il = g_acc[OFF_ILOSS + b] * (1.0f / NI);        // instance loss (W=1)
            float vl = g_acc[OFF_VAR + b];                        // var loss
            float sl = (g_acc[OFF_SBG + b] + 10.0f * g_acc[OFF_SFG + b]) * (1.0f / VV);
            r += il + 10.0f * vl + sl;
            g_acc[OFF_ILOSS + b] = 0.0f;
            g_acc[OFF_VAR + b] = 0.0f;
            g_acc[OFF_SBG + b] = 0.0f;
            g_acc[OFF_SFG + b] = 0.0f;
        }
        out[0] = r * (1.0f / BB);
    }
}

// ---------------------------------------------------------------- launch
extern "C" void kernel_launch(void* const* d_in, const int* in_sizes, int n_in,
                              void* d_out, int out_size) {
    const float* pred = (const float*)d_in[0];
    const int* inst = (const int*)d_in[1];
    const int* lab = (const int*)d_in[2];
    const int* cent = (const int*)d_in[3];

    {
        dim3 g(1024, BB);
        k_stats<<<g, 256>>>(pred, inst, cent);
    }
    k_params<<<1, 64>>>();
    {
        dim3 g(1024, BB, 2);
        k_dist<<<g, 256>>>(pred, inst, lab);
    }
    k_lovasz<<<BB * NI, 256>>>();
    k_final<<<1, 1>>>((float*)d_out);
}

// round 5
// speedup vs baseline: 1.3709x; 1.3709x over previous
#include <cuda_runtime.h>

#define BB 2
#define NCH 7
#define VV 2097152          // 32*256*256
#define NI 16
#define NSG 17
#define NBINS 4096
#define SLOTS 8

// accumulator layout (floats)
#define OFF_CNT   0          // BB*NSG
#define OFF_SSUM  34         // BB*NSG*3
#define OFF_SSQ   136
#define OFF_XYZ   238
#define OFF_CCNT  340
#define OFF_CXYZ  374
#define OFF_VAR   476        // BB
#define OFF_SBG   478
#define OFF_SFG   480
#define OFF_ILOSS 482
#define OFF_S     484        // BB*NI*3
#define OFF_CEN   580        // BB*NI*3
#define ACC_N     676

__device__ float g_acc[ACC_N];                                   // zero-init; self-cleaning
__device__ unsigned long long g_hist[BB * NI * NBINS * SLOTS];   // [b][n][bin][slot], 8.4MB
                                                                 // payload: fg<<32 | bg

__device__ __forceinline__ float fast_tanh(float x) {
    float r;
    asm("tanh.approx.f32 %0, %1;" : "=f"(r) : "f"(x));
    return r;
}

// ---------------------------------------------------------------- stats
// Per-warp fixed-point packed accumulators (5 u64 per id), exact bounds for
// <=256 voxels per warp. grid (1024, BB), 256 thr, 8 consecutive voxels/thread.
__global__ void __launch_bounds__(256) k_stats(const float* __restrict__ pred,
                                               const int* __restrict__ inst,
                                               const int* __restrict__ cent) {
    int b = blockIdx.y;
    __shared__ unsigned long long wacc[8][NSG][5];
    __shared__ float sm[NSG * 10];
    int tid = threadIdx.x;
    int warp = tid >> 5, lane = tid & 31;

    for (int j = tid; j < 8 * NSG * 5; j += 256)
        ((unsigned long long*)wacc)[j] = 0ull;
    for (int j = tid; j < NSG * 10; j += 256) sm[j] = 0.0f;
    __syncthreads();

    const float* sig = pred + ((size_t)b * NCH + 3) * VV;
    const int* ib = inst + (size_t)b * VV;
    const int* cb = cent + (size_t)b * VV;

    int v0 = (blockIdx.x * 256 + tid) * 8;
#pragma unroll
    for (int g = 0; g < 2; g++) {
        int vb = v0 + g * 4;
        float4 f0 = *(const float4*)(sig + vb);
        float4 f1 = *(const float4*)(sig + VV + vb);
        float4 f2 = *(const float4*)(sig + 2 * VV + vb);
        int4 iv = *(const int4*)(ib + vb);
        int4 cv = *(const int4*)(cb + vb);
        float a0[4] = {f0.x, f0.y, f0.z, f0.w};
        float a1[4] = {f1.x, f1.y, f1.z, f1.w};
        float a2[4] = {f2.x, f2.y, f2.z, f2.w};
        int ia[4] = {iv.x, iv.y, iv.z, iv.w};
        int ca[4] = {cv.x, cv.y, cv.z, cv.w};
#pragma unroll
        for (int k = 0; k < 4; k++) {
            int v = vb + k;
            int id = ia[k];
            float s0 = fminf(fmaxf(a0[k], -15.9f), 15.9f);
            float s1 = fminf(fmaxf(a1[k], -15.9f), 15.9f);
            float s2 = fminf(fmaxf(a2[k], -15.9f), 15.9f);
            float x = (float)(v & 255) * (1.0f / 1023.0f);
            float y = (float)((v >> 8) & 255) * (1.0f / 1023.0f);
            float z = (float)(v >> 16) * (1.0f / 31.0f);
            unsigned long long* base = wacc[warp][id];
            unsigned xq = __float2uint_rn(x * 4194304.0f);       // 2^22
            unsigned yq = __float2uint_rn(y * 4194304.0f);
            unsigned zq = __float2uint_rn(z * 2097152.0f);       // 2^21
            unsigned q0 = __float2uint_rn((s0 + 16.0f) * 65536.0f);
            unsigned q1 = __float2uint_rn((s1 + 16.0f) * 65536.0f);
            unsigned q2 = __float2uint_rn((s2 + 16.0f) * 65536.0f);
            unsigned r0 = __float2uint_rn(s0 * s0 * 8192.0f);
            unsigned r1 = __float2uint_rn(s1 * s1 * 8192.0f);
            unsigned r2 = __float2uint_rn(s2 * s2 * 8192.0f);
            atomicAdd(&base[0], (1ull << 40) | (unsigned long long)xq);
            atomicAdd(&base[1], ((unsigned long long)yq << 32) | zq);
            atomicAdd(&base[2], ((unsigned long long)q0 << 32) | q1);
            atomicAdd(&base[3], ((unsigned long long)q2 << 32) | r0);
            atomicAdd(&base[4], ((unsigned long long)r1 << 32) | r2);
            if (ca[k] != 0) {   // centers are ~1-per-volume rare: direct global
                int bi = b * NSG + id;
                atomicAdd(&g_acc[OFF_CCNT + bi], 1.0f);
                atomicAdd(&g_acc[OFF_CXYZ + bi * 3 + 0], x);
                atomicAdd(&g_acc[OFF_CXYZ + bi * 3 + 1], y);
                atomicAdd(&g_acc[OFF_CXYZ + bi * 3 + 2], z);
            }
        }
    }
    __syncthreads();

    // decode per-warp packs -> block-level float accumulation
    if (lane < NSG) {
        unsigned long long p0 = wacc[warp][lane][0];
        unsigned long long p1 = wacc[warp][lane][1];
        unsigned long long p2 = wacc[warp][lane][2];
        unsigned long long p3 = wacc[warp][lane][3];
        unsigned long long p4 = wacc[warp][lane][4];
        float cnt = (float)(unsigned)(p0 >> 40);
        float xs = (float)(p0 & 0xFFFFFFFFFFull) * (1.0f / 4194304.0f);
        float ys = (float)(unsigned)(p1 >> 32) * (1.0f / 4194304.0f);
        float zs = (float)(unsigned)(p1) * (1.0f / 2097152.0f);
        float s0s = (float)(unsigned)(p2 >> 32) * (1.0f / 65536.0f) - 16.0f * cnt;
        float s1s = (float)(unsigned)(p2) * (1.0f / 65536.0f) - 16.0f * cnt;
        float s2s = (float)(unsigned)(p3 >> 32) * (1.0f / 65536.0f) - 16.0f * cnt;
        float r0s = (float)(unsigned)(p3) * (1.0f / 8192.0f);
        float r1s = (float)(unsigned)(p4 >> 32) * (1.0f / 8192.0f);
        float r2s = (float)(unsigned)(p4) * (1.0f / 8192.0f);
        float* d = sm + lane * 10;
        atomicAdd(d + 0, cnt);
        atomicAdd(d + 1, s0s);
        atomicAdd(d + 2, s1s);
        atomicAdd(d + 3, s2s);
        atomicAdd(d + 4, r0s);
        atomicAdd(d + 5, r1s);
        atomicAdd(d + 6, r2s);
        atomicAdd(d + 7, xs);
        atomicAdd(d + 8, ys);
        atomicAdd(d + 9, zs);
    }
    __syncthreads();
    if (tid < NSG * 10) {
        int id = tid / 10, f = tid % 10;
        float vsm = sm[tid];
        if (vsm != 0.0f) {
            int bi = b * NSG + id;
            float* dst;
            if (f == 0)      dst = &g_acc[OFF_CNT  + bi];
            else if (f < 4)  dst = &g_acc[OFF_SSUM + bi * 3 + (f - 1)];
            else if (f < 7)  dst = &g_acc[OFF_SSQ  + bi * 3 + (f - 4)];
            else             dst = &g_acc[OFF_XYZ  + bi * 3 + (f - 7)];
            atomicAdd(dst, vsm);
        }
    }
}

// ---------------------------------------------------------------- params (+ zero stats accumulators)
__global__ void k_params() {
    int t = threadIdx.x;
    if (t >= BB * NSG) return;
    int b = t / NSG, id = t % NSG;
    float cnt = g_acc[OFF_CNT + t];
    float safe = fmaxf(cnt, 1.0f);
    float varsum = 0.0f;
    float m[3];
    float xyz[3], cxyz[3];
#pragma unroll
    for (int c = 0; c < 3; c++) {
        float ss = g_acc[OFF_SSUM + t * 3 + c];
        float sq = g_acc[OFF_SSQ + t * 3 + c];
        float mm = ss / safe;
        m[c] = mm;
        varsum += (sq - 2.0f * mm * ss + cnt * mm * mm) / safe;
        xyz[c] = g_acc[OFF_XYZ + t * 3 + c];
        cxyz[c] = g_acc[OFF_CXYZ + t * 3 + c];
    }
    float ccnt = g_acc[OFF_CCNT + t];
    // zero for next graph replay
    g_acc[OFF_CNT + t] = 0.0f;
    g_acc[OFF_CCNT + t] = 0.0f;
#pragma unroll
    for (int c = 0; c < 3; c++) {
        g_acc[OFF_SSUM + t * 3 + c] = 0.0f;
        g_acc[OFF_SSQ + t * 3 + c] = 0.0f;
        g_acc[OFF_XYZ + t * 3 + c] = 0.0f;
        g_acc[OFF_CXYZ + t * 3 + c] = 0.0f;
    }
    if (id >= 1) {
        atomicAdd(&g_acc[OFF_VAR + b], varsum * (1.0f / (3.0f * NI)));
        bool one = (ccnt == 1.0f);
        int p = (b * NI + (id - 1)) * 3;
#pragma unroll
        for (int c = 0; c < 3; c++) {
            float cen = one ? cxyz[c] : xyz[c] / safe;
            g_acc[OFF_CEN + p + c] = cen;
            g_acc[OFF_S + p + c] = expf(10.0f * m[c]);
        }
    }
}

// ---------------------------------------------------------------- dist + histogram + seed loss
// grid (1024, BB, 4), 256 thr, grid-stride scalar loop (8 iters, 1 voxel/iter).
// blockIdx.z selects 4 of 16 instances -> only 24 param registers live.
__global__ void __launch_bounds__(256) k_dist(const float* __restrict__ pred,
                                              const int* __restrict__ inst,
                                              const int* __restrict__ lab) {
    int b = blockIdx.y;
    int quart = blockIdx.z;          // instances [quart*4, quart*4+4)
    int nbase = quart * 4;

    float c0[4], c1[4], c2[4], s0[4], s1[4], s2[4];
#pragma unroll
    for (int j = 0; j < 4; j++) {
        int p = (b * NI + nbase + j) * 3;
        s0[j] = g_acc[OFF_S + p];
        s1[j] = g_acc[OFF_S + p + 1];
        s2[j] = g_acc[OFF_S + p + 2];
        c0[j] = g_acc[OFF_CEN + p];
        c1[j] = g_acc[OFF_CEN + p + 1];
        c2[j] = g_acc[OFF_CEN + p + 2];
    }

    const float* pb = pred + (size_t)b * NCH * VV;
    const int* ib = inst + (size_t)b * VV;
    const int* lb = lab + (size_t)b * VV;
    unsigned long long* hb = g_hist + (size_t)b * NI * NBINS * SLOTS;
    int slot = threadIdx.x & (SLOTS - 1);

    float accbg = 0.0f, accfg = 0.0f;

    for (int v = blockIdx.x * 256 + threadIdx.x; v < VV; v += 1024 * 256) {
        float x = (float)(v & 255) * (1.0f / 1023.0f);
        float y = (float)((v >> 8) & 255) * (1.0f / 1023.0f);
        float z = (float)(v >> 16) * (1.0f / 31.0f);
        float e0 = fast_tanh(pb[v]) + x;
        float e1 = fast_tanh(pb[VV + v]) + y;
        float e2 = fast_tanh(pb[2 * VV + v]) + z;
        int id = ib[v];
        float down = 0.0f;
#pragma unroll
        for (int j = 0; j < 4; j++) {
            int n = nbase + j;
            float dx = e0 - c0[j], dy = e1 - c1[j], dz = e2 - c2[j];
            float arg = s0[j] * dx * dx + s1[j] * dy * dy + s2[j] * dz * dz;
            float d = __expf(-arg);
            bool fg = (id == n + 1);
            if (fg) down = d;
            float e = fg ? fmaf(-2.0f, d, 2.0f) : 2.0f * d;
            int bin = (int)(e * (NBINS * 0.5f));
            if (bin > NBINS - 1) bin = NBINS - 1;
            atomicAdd(&hb[(((n * NBINS) + bin) << 3) | slot],
                      fg ? (1ull << 32) : 1ull);
        }
        bool own = (id > nbase && id <= nbase + 4);
        bool bg = (quart == 0) && (lb[v] == 0);
        if (own | bg) {
            float sd = 1.0f / (1.0f + __expf(-pb[6 * VV + v]));
            if (own) {
                float t = sd - down;
                accfg += t * t;
            }
            if (bg) accbg += sd * sd;
        }
    }

    __shared__ float r1[256], r2[256];
    int t = threadIdx.x;
    r1[t] = accbg;
    r2[t] = accfg;
    __syncthreads();
    for (int s = 128; s > 0; s >>= 1) {
        if (t < s) { r1[t] += r1[t + s]; r2[t] += r2[t + s]; }
        __syncthreads();
    }
    if (t == 0) {
        if (quart == 0) atomicAdd(&g_acc[OFF_SBG + b], r1[0]);
        atomicAdd(&g_acc[OFF_SFG + b], r2[0]);
    }
}

// ---------------------------------------------------------------- lovasz from histogram (read-only)
// one block per (b,n); 1024 threads; CH=4 bins/thread; shfl-based prefix scan
__global__ void __launch_bounds__(1024) k_lovasz() {
    int bn = blockIdx.x;       // b*16 + n
    int b = bn >> 4;
    const unsigned long long* H = g_hist + (size_t)bn * NBINS * SLOTS;
    const int CH = NBINS / 1024;  // 4
    int t = threadIdx.x;
    int lane = t & 31, warp = t >> 5;

    // load my bins (descending error order: rank r = t*CH+i, bin = NBINS-1-r)
    float fA[CH], bA[CH];
    float locF = 0.0f, locB = 0.0f;
#pragma unroll
    for (int i = 0; i < CH; i++) {
        int bin = NBINS - 1 - (t * CH + i);
        unsigned long long s = 0;
#pragma unroll
        for (int sl = 0; sl < SLOTS; sl++) s += H[(bin << 3) | sl];
        fA[i] = (float)(unsigned)(s >> 32);
        bA[i] = (float)(unsigned)(s & 0xffffffffu);
        locF += fA[i];
        locB += bA[i];
    }

    // warp-level inclusive scan of (locF, locB) in thread order
    float incF = locF, incB = locB;
#pragma unroll
    for (int d = 1; d < 32; d <<= 1) {
        float vF = __shfl_up_sync(0xffffffffu, incF, d);
        float vB = __shfl_up_sync(0xffffffffu, incB, d);
        if (lane >= d) { incF += vF; incB += vB; }
    }
    __shared__ float wF[32], wB[32];
    __shared__ float sred[1024];
    __shared__ int sMinR;
    if (t == 0) sMinR = NBINS;
    if (lane == 31) { wF[warp] = incF; wB[warp] = incB; }
    __syncthreads();
    float offF = 0.0f, offB = 0.0f, G = 0.0f;
#pragma unroll
    for (int w = 0; w < 32; w++) {
        float f = wF[w];
        if (w < warp) { offF += f; offB += wB[w]; }
        G += f;
    }
    float P = offF + incF - locF;   // exclusive prefix (fg)
    float Q = offB + incB - locB;   // exclusive prefix (bg)

    float contrib = 0.0f;
    if (G > 0.0f) {
#pragma unroll
        for (int i = 0; i < CH; i++) {
            float f = fA[i], bb = bA[i];
            if (f > 0.0f || bb > 0.0f) {
                int bin = NBINS - 1 - (t * CH + i);
                float e = ((float)bin + 0.5f) * (2.0f / NBINS);
                float gq = G + Q;
                float num = (G - P) * bb + f * gq;   // cancellation-free jacc delta
                float den = gq * (gq + bb);
                contrib += e * num / den;
                P += f;
                Q += bb;
            }
        }
    } else {  // degenerate: no fg voxels -> loss = max error present
#pragma unroll
        for (int i = 0; i < CH; i++) {
            if (fA[i] > 0.0f || bA[i] > 0.0f) {
                atomicMin(&sMinR, t * CH + i);
                break;
            }
        }
    }
    sred[t] = contrib;
    __syncthreads();
    for (int s2 = 512; s2 > 0; s2 >>= 1) {
        if (t < s2) sred[t] += sred[t + s2];
        __syncthreads();
    }
    if (t == 0) {
        float total = sred[0];
        if (G <= 0.0f && sMinR < NBINS)
            total = ((float)(NBINS - 1 - sMinR) + 0.5f) * (2.0f / NBINS);
        atomicAdd(&g_acc[OFF_ILOSS + b], total);
    }
}

// ---------------------------------------------------------------- wipe hist for next replay
__global__ void k_wipe() {
    int total = BB * NI * NBINS * SLOTS;
    for (int i = blockIdx.x * blockDim.x + threadIdx.x; i < total;
         i += gridDim.x * blockDim.x)
        g_hist[i] = 0ull;
}

// ---------------------------------------------------------------- final combine (+ zero loss accumulators)
__global__ void k_final(float* out) {
    if (threadIdx.x == 0 && blockIdx.x == 0) {
        float r = 0.0f;
        for (int b = 0; b < BB; b++) {
            float il = g_acc[OFF_ILOSS + b] * (1.0f / NI);        // instance loss (W=1)
            float vl = g_acc[OFF_VAR + b];                        // var loss
            float sl = (g_acc[OFF_SBG + b] + 10.0f * g_acc[OFF_SFG + b]) * (1.0f / VV);
            r += il + 10.0f * vl + sl;
            g_acc[OFF_ILOSS + b] = 0.0f;
            g_acc[OFF_VAR + b] = 0.0f;
            g_acc[OFF_SBG + b] = 0.0f;
            g_acc[OFF_SFG + b] = 0.0f;
        }
        out[0] = r * (1.0f / BB);
    }
}

// ---------------------------------------------------------------- launch
extern "C" void kernel_launch(void* const* d_in, const int* in_sizes, int n_in,
                              void* d_out, int out_size) {
    const float* pred = (const float*)d_in[0];
    const int* inst = (const int*)d_in[1];
    const int* lab = (const int*)d_in[2];
    const int* cent = (const int*)d_in[3];

    {
        dim3 g(1024, BB);
        k_stats<<<g, 256>>>(pred, inst, cent);
    }
    k_params<<<1, 64>>>();
    {
        dim3 g(1024, BB, 4);
        k_dist<<<g, 256>>>(pred, inst, lab);
    }
    k_lovasz<<<BB * NI, 1024>>>();
    k_wipe<<<512, 256>>>();
    k_final<<<1, 1>>>((float*)d_out);
}